// round 15
// baseline (speedup 1.0000x reference)
#include <cuda_runtime.h>
#include <cuda_bf16.h>
#include <cstdint>

#define SEQ     512
#define NBATCH  256
#define NSTATE  1024
#define NOUT    256
#define ALPHA   0.1f
#define OMALPHA 0.9f

#define NCTA 128
#define NTHR 256

#define WR_STR 1032                 // bf16; 2064B ≡ 16 mod 128 -> conflict-free LDSM
#define WO_STR 1032
#define TH2_STR 72                  // 144B ≡ 16 mod 128 -> conflict-free LDSM
#define CH2_ELEM (32 * TH2_STR)     // 2304 bf16 per producer tile
#define CH2_B    (CH2_ELEM * 2)     // 4608 B

#define SMEM_WR   (64 * WR_STR)
#define SMEM_TH2  (16 * CH2_ELEM)
#define BUFC_F    (4 * 32 * 33)     // C partials: blk(s,p) x 32 rows x 33 (pad)
#define BUFD_F    (4 * 512)         // D partials: 4 warps x 512
#define SMEM_BYTES ((SMEM_WR + SMEM_TH2) * 2 + (BUFC_F + BUFD_F) * 4 + 64)

__device__ __align__(16) __nv_bfloat16 g_th2[2][8 * 16 * CH2_ELEM];
__device__ unsigned g_flags[NCTA * 32];     // one flag per 128B, monotone

__device__ __forceinline__ unsigned tanh_pack(float lo, float hi) {
    unsigned p, r;
    asm("cvt.rn.bf16x2.f32 %0, %2, %1;" : "=r"(p) : "f"(lo), "f"(hi));
    asm("tanh.approx.bf16x2 %0, %1;" : "=r"(r) : "r"(p));
    return r;
}
__device__ __forceinline__ void stcg_u32(void* p, unsigned v) {
    asm volatile("st.global.cg.b32 [%0], %1;" :: "l"(p), "r"(v));
}
__device__ __forceinline__ void ldsm4(unsigned r[4], unsigned addr) {
    asm volatile("ldmatrix.sync.aligned.m8n8.x4.shared.b16 {%0,%1,%2,%3}, [%4];"
                 : "=r"(r[0]), "=r"(r[1]), "=r"(r[2]), "=r"(r[3]) : "r"(addr));
}
__device__ __forceinline__ void mma16816(float c[4], const unsigned a[4], const unsigned b[2]) {
    asm volatile(
        "mma.sync.aligned.m16n8k16.row.col.f32.bf16.bf16.f32 "
        "{%0,%1,%2,%3},{%4,%5,%6,%7},{%8,%9},{%0,%1,%2,%3};"
        : "+f"(c[0]), "+f"(c[1]), "+f"(c[2]), "+f"(c[3])
        : "r"(a[0]), "r"(a[1]), "r"(a[2]), "r"(a[3]), "r"(b[0]), "r"(b[1]));
}
__device__ __forceinline__ void mbar_init(unsigned mbar, unsigned count) {
    asm volatile("mbarrier.init.shared.b64 [%0], %1;" :: "r"(mbar), "r"(count));
}
__device__ __forceinline__ void mbar_expect_tx(unsigned mbar, unsigned bytes) {
    asm volatile("mbarrier.arrive.expect_tx.shared.b64 _, [%0], %1;"
                 :: "r"(mbar), "r"(bytes) : "memory");
}
__device__ __forceinline__ void mbar_wait(unsigned mbar, unsigned parity) {
    asm volatile(
        "{\n\t.reg .pred P1;\n\t"
        "LAB_W_%=:\n\t"
        "mbarrier.try_wait.parity.acquire.cta.shared::cta.b64 P1, [%0], %1, 0x989680;\n\t"
        "@P1 bra LAB_D_%=;\n\t"
        "bra LAB_W_%=;\n\t"
        "LAB_D_%=:\n\t}"
        :: "r"(mbar), "r"(parity) : "memory");
}
__device__ __forceinline__ void bulk_ldg(unsigned dst_smem, const void* src,
                                         unsigned bytes, unsigned mbar) {
    asm volatile(
        "cp.async.bulk.shared::cta.global.mbarrier::complete_tx::bytes [%0], [%1], %2, [%3];"
        :: "r"(dst_smem), "l"(src), "r"(bytes), "r"(mbar) : "memory");
}

__global__ void __launch_bounds__(NTHR, 1)
rnn_scan_kernel(const float* __restrict__ x, const float* __restrict__ h_init,
                const float* __restrict__ w_r, const float* __restrict__ b_r,
                const float* __restrict__ w_o, const float* __restrict__ b_o,
                float* __restrict__ out)
{
    extern __shared__ char smem_raw[];
    __nv_bfloat16* wr_s = (__nv_bfloat16*)smem_raw;
    __nv_bfloat16* th_s = wr_s + SMEM_WR;            // 16 producer chunks (wo staging in prologue)
    float*         bufC = (float*)(th_s + SMEM_TH2); // C partials
    float*         bufD = bufC + BUFC_F;             // D partials
    unsigned long long* mbars = (unsigned long long*)(bufD + BUFD_F);  // 4 quad mbarriers
    unsigned*      s_base = (unsigned*)(mbars + 4);

    const int cta = blockIdx.x, tid = threadIdx.x;
    const int wid = tid >> 5, lane = tid & 31;
    const int g = lane >> 2, tg = lane & 3;
    const int grp = cta >> 4;          // 8 groups of 16 CTAs (32 batch rows each)
    const int own = cta & 15;
    const int oq  = own >> 2;

    const int row0 = grp * 32;
    const int col0 = own * 64;
    const int nb2 = own * 16;

    // C warps (wid 0-3): position p (n-cols p*32..), split s (k-offset s*32 in chunk)
    const int cp = wid & 1, cs_ = wid >> 1;
    // D warps (wid 4-7): chunk class dw = wid & 3
    const int dw = wid & 3;

    const unsigned th_u32 = (unsigned)__cvta_generic_to_shared(th_s);
    const unsigned wr_u32 = (unsigned)__cvta_generic_to_shared(wr_s);
    const unsigned mb_u32 = (unsigned)__cvta_generic_to_shared(mbars);
    const int l15 = lane & 15, lhi = lane >> 4;
    const unsigned aOff  = ((l15 * TH2_STR + lhi * 8)) * 2;                 // A-frag rows 0-15
    const unsigned bCOff = (((cp * 32 + l15) * WR_STR + lhi * 8)) * 2;      // w_r n-rows
    const unsigned bB_off = ((l15 * WO_STR + lhi * 8)) * 2;                 // w_o staging

    // uniform h ownership: row = tid&31, cols cb8..cb8+7
    const int hrow = tid & 31;
    const int cb8  = (tid >> 5) * 8;
    __nv_bfloat16* th_own = th_s + own * CH2_ELEM;
    const unsigned tile_idx = (unsigned)(grp * 16 + own) * CH2_ELEM;
    const int po = hrow * TH2_STR + cb8;   // element offset of this thread's 8 cols

    // ---- prologue: w_r -> smem ----
    for (int i = tid; i < 64 * 256; i += NTHR) {
        int n = i >> 8, c4 = i & 255;
        float4 v = ((const float4*)(w_r + (col0 + n) * NSTATE))[c4];
        __nv_bfloat16* d = wr_s + n * WR_STR + c4 * 4;
        d[0] = __float2bfloat16(v.x); d[1] = __float2bfloat16(v.y);
        d[2] = __float2bfloat16(v.z); d[3] = __float2bfloat16(v.w);
    }
    // stage w_o in th_s, pull fragments into D-warp registers
    for (int i = tid; i < 16 * 256; i += NTHR) {
        int n = i >> 8, c4 = i & 255;
        float4 v = ((const float4*)(w_o + (nb2 + n) * NSTATE))[c4];
        __nv_bfloat16* d = th_s + n * WO_STR + c4 * 4;
        d[0] = __float2bfloat16(v.x); d[1] = __float2bfloat16(v.y);
        d[2] = __float2bfloat16(v.z); d[3] = __float2bfloat16(v.w);
    }
    __syncthreads();
    unsigned bD[64];   // D warps: w_o frags for chunks c = cs*4 + dw, kk 0..3
    if (wid >= 4) {
        #pragma unroll
        for (int cs = 0; cs < 4; cs++) {
            const int c = cs * 4 + dw;
            #pragma unroll
            for (int kk = 0; kk < 4; kk++)
                ldsm4(&bD[(cs * 4 + kk) * 4], th_u32 + bB_off + (c * 64 + kk * 16) * 2);
        }
    }
    __syncthreads();

    float br[8], h[8];
    #pragma unroll
    for (int j = 0; j < 8; j++) {
        br[j] = b_r[col0 + cb8 + j];
        h[j]  = h_init[(row0 + hrow) * NSTATE + col0 + cb8 + j];
    }
    const float bo = b_o[nb2 + (tid & 15)];

    // publish th[0]
    {
        __nv_bfloat16* gt = g_th2[0] + tile_idx;
        #pragma unroll
        for (int jj = 0; jj < 4; jj++) {
            unsigned v = tanh_pack(h[2 * jj], h[2 * jj + 1]);
            *(unsigned*)(th_own + po + 2 * jj) = v;
            stcg_u32(gt + po + 2 * jj, v);
        }
    }

    if (tid == 0) {
        *s_base = g_flags[cta * 32];
        mbar_init(mb_u32,      1);
        mbar_init(mb_u32 + 8,  1);
        mbar_init(mb_u32 + 16, 1);
        mbar_init(mb_u32 + 24, 1);
    }
    __syncthreads();
    const unsigned base = *s_base;
    unsigned par = 0;

    if (tid == 0)
        asm volatile("st.release.gpu.global.b32 [%0], %1;"
                     :: "l"(g_flags + cta * 32), "r"(base + 1) : "memory");
    if (wid == 0) {
        if (lane < 4)
            mbar_expect_tx(mb_u32 + lane * 8, CH2_B * ((lane == oq) ? 3u : 4u));
        if (lane < 16 && lane != own) {
            const unsigned* f = g_flags + (grp * 16 + lane) * 32;
            unsigned v;
            do { asm volatile("ld.acquire.gpu.global.b32 %0, [%1];" : "=r"(v) : "l"(f) : "memory"); }
            while (v < base + 1);
            bulk_ldg(th_u32 + lane * CH2_B,
                     g_th2[0] + (grp * 16 + lane) * CH2_ELEM, CH2_B,
                     mb_u32 + (lane >> 2) * 8);
        }
    }

    // ---- scan: iter i consumes th[i]; C -> h_{i+1}; D -> err_{i-1} ----
    for (int i = 0; i <= SEQ; i++) {
        const bool doC = (i < SEQ);
        const bool doD = (i > 0);

        float Ca[8][4];     // C warps: [mb*4+nb][4]
        float D[4][4];      // D warps
        #pragma unroll
        for (int q = 0; q < 8; q++) { Ca[q][0]=0; Ca[q][1]=0; Ca[q][2]=0; Ca[q][3]=0; }
        #pragma unroll
        for (int q = 0; q < 4; q++) { D[q][0]=0; D[q][1]=0; D[q][2]=0; D[q][3]=0; }

        float xv0 = 0.f, xv1 = 0.f; int oi0 = 0, oi1 = 0;
        if (doD) {
            oi0 = ((i - 1) * NBATCH + row0 + (tid >> 4)) * NOUT + nb2 + (tid & 15);
            oi1 = oi0 + 16 * NOUT;
            xv0 = __ldg(x + oi0);
            xv1 = __ldg(x + oi1);
        }

        unsigned waited = 0;
        #pragma unroll
        for (int j = 0; j < 16; j++) {
            const int c = (own + j) & 15;
            if (c != own) {
                const int q = c >> 2;
                if (!((waited >> q) & 1)) { mbar_wait(mb_u32 + q * 8, par); waited |= 1u << q; }
            }
            const unsigned cur = th_u32 + c * CH2_B;
            if (doC && wid < 4) {     // m32n32, K = s*32..s*32+32 of this chunk
                #pragma unroll
                for (int kk = 0; kk < 2; kk++) {
                    const int kl = cs_ * 32 + kk * 16;           // k within chunk
                    unsigned a0[4], a1[4], bq0[4], bq1[4];
                    ldsm4(a0, cur + aOff + kl * 2);
                    ldsm4(a1, cur + aOff + kl * 2 + 16 * TH2_STR * 2);
                    const unsigned wb = wr_u32 + bCOff + (c * 64 + kl) * 2;
                    ldsm4(bq0, wb);
                    ldsm4(bq1, wb + 16 * WR_STR * 2);
                    unsigned b0[2] = { bq0[0], bq0[2] }, b1[2] = { bq0[1], bq0[3] };
                    unsigned b2[2] = { bq1[0], bq1[2] }, b3[2] = { bq1[1], bq1[3] };
                    mma16816(Ca[0], a0, b0); mma16816(Ca[1], a0, b1);
                    mma16816(Ca[2], a0, b2); mma16816(Ca[3], a0, b3);
                    mma16816(Ca[4], a1, b0); mma16816(Ca[5], a1, b1);
                    mma16816(Ca[6], a1, b2); mma16816(Ca[7], a1, b3);
                }
            }
            if (doD && wid >= 4 && (c & 3) == dw) {   // whole chunk K=64
                const int cs = c >> 2;
                #pragma unroll
                for (int kk = 0; kk < 4; kk++) {
                    unsigned a0[4], a1[4];
                    ldsm4(a0, cur + aOff + kk * 32);
                    ldsm4(a1, cur + aOff + kk * 32 + 16 * TH2_STR * 2);
                    const unsigned* b = &bD[(cs * 4 + kk) * 4];
                    unsigned b0[2] = { b[0], b[2] }, b1[2] = { b[1], b[3] };
                    mma16816(D[0], a0, b0);
                    mma16816(D[1], a0, b1);
                    mma16816(D[2], a1, b0);
                    mma16816(D[3], a1, b1);
                }
            }
        }
        par ^= 1;
        __syncthreads();   // S1: all chunk reads done; buffers writable

        if (doC && wid < 4) {   // park C partials: blk = cs_*2+cp, stride 33
            float* rc = bufC + (cs_ * 2 + cp) * (32 * 33);
            #pragma unroll
            for (int q = 0; q < 8; q++) {
                int mb = q >> 2, nb = q & 3;
                #pragma unroll
                for (int jj = 0; jj < 4; jj++) {
                    int m = mb * 16 + g + ((jj >> 1) << 3);
                    int n = nb * 8 + 2 * tg + (jj & 1);
                    rc[m * 33 + n] = Ca[q][jj];
                }
            }
        }
        if (doD && wid >= 4) {  // park D partials
            float* rw = bufD + dw * 512;
            #pragma unroll
            for (int q = 0; q < 4; q++) {
                int mi = q >> 1, ni = q & 1;
                #pragma unroll
                for (int jj = 0; jj < 4; jj++)
                    rw[(mi * 16 + g + ((jj >> 1) << 3)) * 16 + ni * 8 + 2 * tg + (jj & 1)] = D[q][jj];
            }
        }
        __syncthreads();   // S2: partials visible

        if (doC) {         // uniform h-update + bf16x2 tanh + publish (all 256 threads)
            __nv_bfloat16* gt = g_th2[(i + 1) & 1] + tile_idx;
            #pragma unroll
            for (int jj = 0; jj < 4; jj++) {
                const int n0 = cb8 + 2 * jj;
                const int p = n0 >> 5, nl = n0 & 31;
                float s0 = bufC[p * (32 * 33) + hrow * 33 + nl]
                         + bufC[(2 + p) * (32 * 33) + hrow * 33 + nl];
                float s1 = bufC[p * (32 * 33) + hrow * 33 + nl + 1]
                         + bufC[(2 + p) * (32 * 33) + hrow * 33 + nl + 1];
                h[2 * jj]     = OMALPHA * h[2 * jj]     + ALPHA * (s0 + br[2 * jj]);
                h[2 * jj + 1] = OMALPHA * h[2 * jj + 1] + ALPHA * (s1 + br[2 * jj + 1]);
                unsigned v = tanh_pack(h[2 * jj], h[2 * jj + 1]);
                *(unsigned*)(th_own + po + 2 * jj) = v;
                stcg_u32(gt + po + 2 * jj, v);
            }
        }
        __syncthreads();   // S3: publish + parks visible

        if (doC) {
            if (tid == 0)
                asm volatile("st.release.gpu.global.b32 [%0], %1;"
                             :: "l"(g_flags + cta * 32), "r"(base + i + 2) : "memory");
            if (wid == 0) {
                const unsigned tgt = base + i + 2;
                if (lane < 4)
                    mbar_expect_tx(mb_u32 + lane * 8, CH2_B * ((lane == oq) ? 3u : 4u));
                if (lane < 16 && lane != own) {
                    const unsigned* f = g_flags + (grp * 16 + lane) * 32;
                    unsigned v;
                    do { asm volatile("ld.acquire.gpu.global.b32 %0, [%1];" : "=r"(v) : "l"(f) : "memory"); }
                    while (v < tgt);
                    bulk_ldg(th_u32 + lane * CH2_B,
                             g_th2[(i + 1) & 1] + (grp * 16 + lane) * CH2_ELEM, CH2_B,
                             mb_u32 + (lane >> 2) * 8);
                }
            }
        }

        if (doD) {         // epilogue (warps 1-7 overlap warp0's poll/TMA)
            float s0 = 0.f, s1 = 0.f;
            #pragma unroll
            for (int w = 0; w < 4; w++) {
                s0 += bufD[w * 512 + tid];
                s1 += bufD[w * 512 + tid + 256];
            }
            out[oi0] = s0 + bo - xv0;
            out[oi1] = s1 + bo - xv1;
        }
    }
}

extern "C" void kernel_launch(void* const* d_in, const int* in_sizes, int n_in,
                              void* d_out, int out_size) {
    const float* x      = (const float*)d_in[0];
    const float* h_init = (const float*)d_in[1];
    const float* w_r    = (const float*)d_in[2];
    const float* b_r    = (const float*)d_in[3];
    const float* w_o    = (const float*)d_in[4];
    const float* b_o    = (const float*)d_in[5];
    float* out = (float*)d_out;

    static bool configured = false;
    if (!configured) {
        cudaFuncSetAttribute(rnn_scan_kernel,
                             cudaFuncAttributeMaxDynamicSharedMemorySize, SMEM_BYTES);
        configured = true;
    }
    rnn_scan_kernel<<<NCTA, NTHR, SMEM_BYTES>>>(x, h_init, w_r, b_r, w_o, b_o, out);
}

// round 16
// speedup vs baseline: 1.0546x; 1.0546x over previous
#include <cuda_runtime.h>
#include <cuda_bf16.h>
#include <cstdint>

#define SEQ     512
#define NBATCH  256
#define NSTATE  1024
#define NOUT    256
#define ALPHA   0.1f
#define OMALPHA 0.9f

#define NCTA 128
#define NTHR 256

#define WO_STR 1032                 // bf16 staging stride (prologue only)
#define TH2_STR 72                  // bf16 tile: 144B rows, ≡16 mod 128
#define WR8_STR 1040                // fp8 w_r: 1040B rows, ≡16 mod 128

#define SLOT_B   9216               // per-producer tile: bf16(4608) + fp8(4608)
#define FP8_OFF  4608
#define SMEM_WR8 (64 * WR8_STR)     // bytes
#define SMEM_TH  (16 * SLOT_B)      // bytes
#define REDD_F   (8 * 512)
#define SMEM_BYTES (SMEM_WR8 + SMEM_TH + REDD_F * 4 + 64)

__device__ __align__(16) unsigned char g_th3[2][8 * 16 * SLOT_B];
__device__ unsigned g_flags[NCTA * 32];     // one flag per 128B, monotone

__device__ __forceinline__ float tanh_f(float v) {
    float r; asm("tanh.approx.f32 %0, %1;" : "=f"(r) : "f"(v)); return r;
}
__device__ __forceinline__ unsigned pack_bf2(float lo, float hi) {
    unsigned p;
    asm("cvt.rn.bf16x2.f32 %0, %2, %1;" : "=r"(p) : "f"(lo), "f"(hi));
    return p;
}
__device__ __forceinline__ unsigned short pack_e4m3(float lo, float hi) {
    unsigned short p;
    asm("cvt.rn.satfinite.e4m3x2.f32 %0, %2, %1;" : "=h"(p) : "f"(lo), "f"(hi));
    return p;
}
__device__ __forceinline__ void stcg_u32(void* p, unsigned v) {
    asm volatile("st.global.cg.b32 [%0], %1;" :: "l"(p), "r"(v));
}
__device__ __forceinline__ void stcg_u16(void* p, unsigned short v) {
    asm volatile("st.global.cg.b16 [%0], %1;" :: "l"(p), "h"(v));
}
__device__ __forceinline__ void ldsm4(unsigned r[4], unsigned addr) {
    asm volatile("ldmatrix.sync.aligned.m8n8.x4.shared.b16 {%0,%1,%2,%3}, [%4];"
                 : "=r"(r[0]), "=r"(r[1]), "=r"(r[2]), "=r"(r[3]) : "r"(addr));
}
__device__ __forceinline__ void mma_bf16(float c[4], const unsigned a[4], const unsigned b[2]) {
    asm volatile(
        "mma.sync.aligned.m16n8k16.row.col.f32.bf16.bf16.f32 "
        "{%0,%1,%2,%3},{%4,%5,%6,%7},{%8,%9},{%0,%1,%2,%3};"
        : "+f"(c[0]), "+f"(c[1]), "+f"(c[2]), "+f"(c[3])
        : "r"(a[0]), "r"(a[1]), "r"(a[2]), "r"(a[3]), "r"(b[0]), "r"(b[1]));
}
__device__ __forceinline__ void mma_fp8(float c[4], const unsigned a[4], const unsigned b[2]) {
    asm volatile(
        "mma.sync.aligned.m16n8k32.row.col.f32.e4m3.e4m3.f32 "
        "{%0,%1,%2,%3},{%4,%5,%6,%7},{%8,%9},{%0,%1,%2,%3};"
        : "+f"(c[0]), "+f"(c[1]), "+f"(c[2]), "+f"(c[3])
        : "r"(a[0]), "r"(a[1]), "r"(a[2]), "r"(a[3]), "r"(b[0]), "r"(b[1]));
}
__device__ __forceinline__ void mbar_init(unsigned mbar, unsigned count) {
    asm volatile("mbarrier.init.shared.b64 [%0], %1;" :: "r"(mbar), "r"(count));
}
__device__ __forceinline__ void mbar_expect_tx(unsigned mbar, unsigned bytes) {
    asm volatile("mbarrier.arrive.expect_tx.shared.b64 _, [%0], %1;"
                 :: "r"(mbar), "r"(bytes) : "memory");
}
__device__ __forceinline__ void mbar_wait(unsigned mbar, unsigned parity) {
    asm volatile(
        "{\n\t.reg .pred P1;\n\t"
        "LAB_W_%=:\n\t"
        "mbarrier.try_wait.parity.acquire.cta.shared::cta.b64 P1, [%0], %1, 0x989680;\n\t"
        "@P1 bra LAB_D_%=;\n\t"
        "bra LAB_W_%=;\n\t"
        "LAB_D_%=:\n\t}"
        :: "r"(mbar), "r"(parity) : "memory");
}
__device__ __forceinline__ void bulk_ldg(unsigned dst_smem, const void* src,
                                         unsigned bytes, unsigned mbar) {
    asm volatile(
        "cp.async.bulk.shared::cta.global.mbarrier::complete_tx::bytes [%0], [%1], %2, [%3];"
        :: "r"(dst_smem), "l"(src), "r"(bytes), "r"(mbar) : "memory");
}

__global__ void __launch_bounds__(NTHR, 1)
rnn_scan_kernel(const float* __restrict__ x, const float* __restrict__ h_init,
                const float* __restrict__ w_r, const float* __restrict__ b_r,
                const float* __restrict__ w_o, const float* __restrict__ b_o,
                float* __restrict__ out)
{
    extern __shared__ char smem_raw[];
    unsigned char* wr8_s = (unsigned char*)smem_raw;          // fp8 w_r [64 n][1024 k]
    unsigned char* th_s  = wr8_s + SMEM_WR8;                  // 16 slots x 9216B
    float*         redD  = (float*)(th_s + SMEM_TH);          // 8 x 512
    unsigned long long* mbars = (unsigned long long*)(redD + REDD_F);
    unsigned*      s_base = (unsigned*)(mbars + 4);

    const int cta = blockIdx.x, tid = threadIdx.x;
    const int wid = tid >> 5, lane = tid & 31;
    const int g = lane >> 2, tg = lane & 3;
    const int grp = cta >> 4;
    const int own = cta & 15;
    const int oq  = own >> 2;

    const int row0 = grp * 32;
    const int col0 = own * 64;
    const int nb2 = own * 16;

    const int wm = (wid >> 2) * 16, wn = (wid & 3) * 16;   // 2x4 warp grid, m16n16
    const int lr0 = wm + g;                                // local C rows
    const int cbl = wn + 2 * tg;                           // local C col base
    const int cbg = col0 + cbl;

    const unsigned th_u32  = (unsigned)__cvta_generic_to_shared(th_s);
    const unsigned wr8_u32 = (unsigned)__cvta_generic_to_shared(wr8_s);
    const unsigned mb_u32  = (unsigned)__cvta_generic_to_shared(mbars);
    const int l15 = lane & 15, lhi = lane >> 4;
    const unsigned aC_off = (unsigned)((wm + l15) * 144 + lhi * 16) + FP8_OFF; // fp8 A
    const unsigned bC_off = (unsigned)((wn + l15) * WR8_STR + lhi * 16);       // fp8 B
    const unsigned aB_off = (unsigned)((l15 * TH2_STR + lhi * 8) * 2);         // bf16 A
    const unsigned bS_off = (unsigned)((l15 * WO_STR + lhi * 8) * 2);          // staging

    unsigned char* th_own = th_s + own * SLOT_B;
    unsigned char* gslot0 = g_th3[0] + (grp * 16 + own) * SLOT_B;
    unsigned char* gslot1 = g_th3[1] + (grp * 16 + own) * SLOT_B;
    // per-thread publish byte offsets within slot
    const unsigned pb0 = (unsigned)(lr0 * 144 + cbl * 2);          // bf16 (pair)
    const unsigned pf0 = (unsigned)(FP8_OFF + lr0 * 144 + cbl);    // fp8 (pair)

    // ---- prologue: w_r -> fp8 smem ----
    for (int i = tid; i < 64 * 256; i += NTHR) {
        int n = i >> 8, c4 = i & 255;
        float4 v = ((const float4*)(w_r + (col0 + n) * NSTATE))[c4];
        unsigned short p01 = pack_e4m3(v.x, v.y);
        unsigned short p23 = pack_e4m3(v.z, v.w);
        *(unsigned*)(wr8_s + n * WR8_STR + c4 * 4) = (unsigned)p01 | ((unsigned)p23 << 16);
    }
    // stage w_o (bf16) in tile region, pull fragments into registers
    for (int i = tid; i < 16 * 256; i += NTHR) {
        int n = i >> 8, c4 = i & 255;
        float4 v = ((const float4*)(w_o + (nb2 + n) * NSTATE))[c4];
        __nv_bfloat16* d = (__nv_bfloat16*)th_s + n * WO_STR + c4 * 4;
        d[0] = __float2bfloat16(v.x); d[1] = __float2bfloat16(v.y);
        d[2] = __float2bfloat16(v.z); d[3] = __float2bfloat16(v.w);
    }
    __syncthreads();
    unsigned bD[32];   // w_o frags for chunks c = wid and c = wid+8
    #pragma unroll
    for (int cs = 0; cs < 2; cs++)
        #pragma unroll
        for (int kk = 0; kk < 4; kk++)
            ldsm4(&bD[(cs * 4 + kk) * 4],
                  th_u32 + bS_off + (((wid + cs * 8) * 64) + kk * 16) * 2);
    __syncthreads();

    float br[4] = { b_r[cbg], b_r[cbg + 1], b_r[cbg + 8], b_r[cbg + 9] };
    const float bo = b_o[nb2 + (tid & 15)];
    const int r0g = row0 + lr0, r1g = r0g + 8;
    float h[8];
    h[0] = h_init[r0g * NSTATE + cbg];     h[1] = h_init[r0g * NSTATE + cbg + 1];
    h[2] = h_init[r1g * NSTATE + cbg];     h[3] = h_init[r1g * NSTATE + cbg + 1];
    h[4] = h_init[r0g * NSTATE + cbg + 8]; h[5] = h_init[r0g * NSTATE + cbg + 9];
    h[6] = h_init[r1g * NSTATE + cbg + 8]; h[7] = h_init[r1g * NSTATE + cbg + 9];

    // publish th[0] (bf16 + fp8, smem + global)
    {
        float t0 = tanh_f(h[0]), t1 = tanh_f(h[1]), t2 = tanh_f(h[2]), t3 = tanh_f(h[3]);
        float t4 = tanh_f(h[4]), t5 = tanh_f(h[5]), t6 = tanh_f(h[6]), t7 = tanh_f(h[7]);
        unsigned b0 = pack_bf2(t0, t1), b1 = pack_bf2(t2, t3);
        unsigned b2 = pack_bf2(t4, t5), b3 = pack_bf2(t6, t7);
        unsigned short f0 = pack_e4m3(t0, t1), f1 = pack_e4m3(t2, t3);
        unsigned short f2 = pack_e4m3(t4, t5), f3 = pack_e4m3(t6, t7);
        *(unsigned*)(th_own + pb0)             = b0;
        *(unsigned*)(th_own + pb0 + 8 * 144)   = b1;
        *(unsigned*)(th_own + pb0 + 16)        = b2;
        *(unsigned*)(th_own + pb0 + 8 * 144 + 16) = b3;
        *(unsigned short*)(th_own + pf0)           = f0;
        *(unsigned short*)(th_own + pf0 + 8 * 144) = f1;
        *(unsigned short*)(th_own + pf0 + 8)       = f2;
        *(unsigned short*)(th_own + pf0 + 8 * 144 + 8) = f3;
        stcg_u32(gslot0 + pb0,              b0);
        stcg_u32(gslot0 + pb0 + 8 * 144,    b1);
        stcg_u32(gslot0 + pb0 + 16,         b2);
        stcg_u32(gslot0 + pb0 + 8 * 144 + 16, b3);
        stcg_u16(gslot0 + pf0,              f0);
        stcg_u16(gslot0 + pf0 + 8 * 144,    f1);
        stcg_u16(gslot0 + pf0 + 8,          f2);
        stcg_u16(gslot0 + pf0 + 8 * 144 + 8, f3);
    }

    if (tid == 0) {
        *s_base = g_flags[cta * 32];
        mbar_init(mb_u32,      1);
        mbar_init(mb_u32 + 8,  1);
        mbar_init(mb_u32 + 16, 1);
        mbar_init(mb_u32 + 24, 1);
    }
    __syncthreads();
    const unsigned base = *s_base;
    unsigned par = 0;

    if (tid == 0)
        asm volatile("st.release.gpu.global.b32 [%0], %1;"
                     :: "l"(g_flags + cta * 32), "r"(base + 1) : "memory");
    if (wid == 0) {
        if (lane < 4)
            mbar_expect_tx(mb_u32 + lane * 8, SLOT_B * ((lane == oq) ? 3u : 4u));
        if (lane < 16 && lane != own) {
            const unsigned* f = g_flags + (grp * 16 + lane) * 32;
            unsigned v;
            do { asm volatile("ld.acquire.gpu.global.b32 %0, [%1];" : "=r"(v) : "l"(f) : "memory"); }
            while (v < base + 1);
            bulk_ldg(th_u32 + lane * SLOT_B,
                     g_th3[0] + (grp * 16 + lane) * SLOT_B, SLOT_B,
                     mb_u32 + (lane >> 2) * 8);
        }
    }

    // ---- scan: iter i consumes th[i]; C (fp8) -> h_{i+1}; D (bf16) -> err_{i-1} ----
    for (int i = 0; i <= SEQ; i++) {
        const bool doC = (i < SEQ);
        const bool doD = (i > 0);

        float Ce0[4] = {0,0,0,0}, Ce1[4] = {0,0,0,0};
        float Co0[4] = {0,0,0,0}, Co1[4] = {0,0,0,0};
        float D[4][4];
        #pragma unroll
        for (int q = 0; q < 4; q++) { D[q][0]=0; D[q][1]=0; D[q][2]=0; D[q][3]=0; }

        float xv0 = 0.f, xv1 = 0.f; int oi0 = 0, oi1 = 0;
        if (doD) {
            oi0 = ((i - 1) * NBATCH + row0 + (tid >> 4)) * NOUT + nb2 + (tid & 15);
            oi1 = oi0 + 16 * NOUT;
            xv0 = __ldg(x + oi0);
            xv1 = __ldg(x + oi1);
        }

        unsigned waited = 0;
        #pragma unroll
        for (int j = 0; j < 16; j++) {
            const int c = (own + j) & 15;
            if (c != own) {
                const int q = c >> 2;
                if (!((waited >> q) & 1)) { mbar_wait(mb_u32 + q * 8, par); waited |= 1u << q; }
            }
            const unsigned cur = th_u32 + c * SLOT_B;
            if (doC) {      // fp8: K=64 per chunk in 2 k32 steps
                const unsigned ab = cur + aC_off;
                const unsigned bb = wr8_u32 + bC_off + c * 64;
                unsigned a0[4], a1[4], bq0[4], bq1[4];
                ldsm4(a0, ab);
                ldsm4(bq0, bb);
                ldsm4(a1, ab + 32);
                ldsm4(bq1, bb + 32);
                unsigned e0[2] = { bq0[0], bq0[2] }, e1[2] = { bq0[1], bq0[3] };
                unsigned o0[2] = { bq1[0], bq1[2] }, o1[2] = { bq1[1], bq1[3] };
                mma_fp8(Ce0, a0, e0);
                mma_fp8(Ce1, a0, e1);
                mma_fp8(Co0, a1, o0);
                mma_fp8(Co1, a1, o1);
            }
            if (doD && (c & 7) == wid) {    // bf16: whole chunk K=64
                const int cs = c >> 3;
                #pragma unroll
                for (int kk = 0; kk < 4; kk++) {
                    unsigned a0[4], a1[4];
                    ldsm4(a0, cur + aB_off + kk * 32);
                    ldsm4(a1, cur + aB_off + kk * 32 + 16 * TH2_STR * 2);
                    const unsigned* b = &bD[(cs * 4 + kk) * 4];
                    unsigned b0[2] = { b[0], b[2] }, b1[2] = { b[1], b[3] };
                    mma_bf16(D[0], a0, b0);
                    mma_bf16(D[1], a0, b1);
                    mma_bf16(D[2], a1, b0);
                    mma_bf16(D[3], a1, b1);
                }
            }
        }
        par ^= 1;
        __syncthreads();   // S1: all chunk reads complete

        if (doD) {         // park D partials
            float* rw = redD + wid * 512;
            #pragma unroll
            for (int q = 0; q < 4; q++) {
                int mi = q >> 1, ni = q & 1;
                #pragma unroll
                for (int jj = 0; jj < 4; jj++)
                    rw[(mi * 16 + g + ((jj >> 1) << 3)) * 16 + ni * 8 + 2 * tg + (jj & 1)] = D[q][jj];
            }
        }

        if (doC) {         // h update + publish th[i+1]
            #pragma unroll
            for (int j = 0; j < 4; j++) {
                h[j]     = OMALPHA * h[j]     + ALPHA * (Ce0[j] + Co0[j] + br[j & 1]);
                h[4 + j] = OMALPHA * h[4 + j] + ALPHA * (Ce1[j] + Co1[j] + br[2 + (j & 1)]);
            }
            float t0 = tanh_f(h[0]), t1 = tanh_f(h[1]), t2 = tanh_f(h[2]), t3 = tanh_f(h[3]);
            float t4 = tanh_f(h[4]), t5 = tanh_f(h[5]), t6 = tanh_f(h[6]), t7 = tanh_f(h[7]);
            unsigned b0 = pack_bf2(t0, t1), b1 = pack_bf2(t2, t3);
            unsigned b2 = pack_bf2(t4, t5), b3 = pack_bf2(t6, t7);
            unsigned short f0 = pack_e4m3(t0, t1), f1 = pack_e4m3(t2, t3);
            unsigned short f2 = pack_e4m3(t4, t5), f3 = pack_e4m3(t6, t7);
            *(unsigned*)(th_own + pb0)             = b0;
            *(unsigned*)(th_own + pb0 + 8 * 144)   = b1;
            *(unsigned*)(th_own + pb0 + 16)        = b2;
            *(unsigned*)(th_own + pb0 + 8 * 144 + 16) = b3;
            *(unsigned short*)(th_own + pf0)           = f0;
            *(unsigned short*)(th_own + pf0 + 8 * 144) = f1;
            *(unsigned short*)(th_own + pf0 + 8)       = f2;
            *(unsigned short*)(th_own + pf0 + 8 * 144 + 8) = f3;
            unsigned char* gt = ((i & 1) ? gslot0 : gslot1);
            stcg_u32(gt + pb0,              b0);
            stcg_u32(gt + pb0 + 8 * 144,    b1);
            stcg_u32(gt + pb0 + 16,         b2);
            stcg_u32(gt + pb0 + 8 * 144 + 16, b3);
            stcg_u16(gt + pf0,              f0);
            stcg_u16(gt + pf0 + 8 * 144,    f1);
            stcg_u16(gt + pf0 + 8,          f2);
            stcg_u16(gt + pf0 + 8 * 144 + 8, f3);
        }
        __syncthreads();   // S2: publish + parks visible

        if (doC) {
            if (tid == 0)
                asm volatile("st.release.gpu.global.b32 [%0], %1;"
                             :: "l"(g_flags + cta * 32), "r"(base + i + 2) : "memory");
            if (wid == 0) {
                const unsigned tgt = base + i + 2;
                if (lane < 4)
                    mbar_expect_tx(mb_u32 + lane * 8, SLOT_B * ((lane == oq) ? 3u : 4u));
                if (lane < 16 && lane != own) {
                    const unsigned* f = g_flags + (grp * 16 + lane) * 32;
                    unsigned v;
                    do { asm volatile("ld.acquire.gpu.global.b32 %0, [%1];" : "=r"(v) : "l"(f) : "memory"); }
                    while (v < tgt);
                    bulk_ldg(th_u32 + lane * SLOT_B,
                             g_th3[(i + 1) & 1] + (grp * 16 + lane) * SLOT_B, SLOT_B,
                             mb_u32 + (lane >> 2) * 8);
                }
            }
        }

        if (doD) {         // epilogue overlaps warp0's poll/TMA
            float s0 = 0.f, s1 = 0.f;
            #pragma unroll
            for (int w = 0; w < 8; w++) {
                s0 += redD[w * 512 + tid];
                s1 += redD[w * 512 + tid + 256];
            }
            out[oi0] = s0 + bo - xv0;
            out[oi1] = s1 + bo - xv1;
        }
    }
}

extern "C" void kernel_launch(void* const* d_in, const int* in_sizes, int n_in,
                              void* d_out, int out_size) {
    const float* x      = (const float*)d_in[0];
    const float* h_init = (const float*)d_in[1];
    const float* w_r    = (const float*)d_in[2];
    const float* b_r    = (const float*)d_in[3];
    const float* w_o    = (const float*)d_in[4];
    const float* b_o    = (const float*)d_in[5];
    float* out = (float*)d_out;

    static bool configured = false;
    if (!configured) {
        cudaFuncSetAttribute(rnn_scan_kernel,
                             cudaFuncAttributeMaxDynamicSharedMemorySize, SMEM_BYTES);
        configured = true;
    }
    rnn_scan_kernel<<<NCTA, NTHR, SMEM_BYTES>>>(x, h_init, w_r, b_r, w_o, b_o, out);
}